// round 2
// baseline (speedup 1.0000x reference)
#include <cuda_runtime.h>
#include <cuda_bf16.h>
#include <math.h>

// Problem constants
#define B   64
#define T   2048
#define D   256
#define V   256

// Scratch in device globals (no allocations allowed)
__device__ float g_EWx[V * D];            // E @ Wx^T
__device__ float g_EG [V * D];            // sigmoid(E @ Wz^T)
__device__ float g_out[(size_t)B * T * D]; // h_t * gate_t   (134 MB)

// ---------------------------------------------------------------------------
// Kernel 1: precompute token tables.  EWx[v][e] = sum_d E[v][d] * Wx[e][d]
// ---------------------------------------------------------------------------
__global__ __launch_bounds__(256)
void precompute_tables(const float* __restrict__ E,
                       const float* __restrict__ Wx,
                       const float* __restrict__ Wz) {
    __shared__ float ev[D];
    const int v = blockIdx.x;
    const int e = threadIdx.x;
    ev[e] = E[(v << 8) + e];
    __syncthreads();

    const float* wxr = Wx + (e << 8);
    const float* wzr = Wz + (e << 8);
    float ax0 = 0.f, ax1 = 0.f, az0 = 0.f, az1 = 0.f;
#pragma unroll 8
    for (int d = 0; d < D; d += 2) {
        float e0 = ev[d], e1 = ev[d + 1];
        ax0 += e0 * wxr[d];     az0 += e0 * wzr[d];
        ax1 += e1 * wxr[d + 1]; az1 += e1 * wzr[d + 1];
    }
    float ax = ax0 + ax1;
    float az = az0 + az1;
    g_EWx[(v << 8) + e] = ax;
    g_EG [(v << 8) + e] = 1.0f / (1.0f + expf(-az));
}

// ---------------------------------------------------------------------------
// Kernel 2: recurrence. One CTA per batch element, 256 threads (one per dim).
// Wh row d: cols [0,160) live in registers, cols [160,256) in SMEM
// (row stride 100 floats -> conflict-free LDS.128).
// ---------------------------------------------------------------------------
#define WREG_K   160                     // weight columns held in registers
#define WSM_K    96                      // weight columns held in SMEM
#define WSM_STR  100                     // padded SMEM row stride (floats)
#define RNN_SMEM_FLOATS (D * WSM_STR + 2 * D + (T + 4))
#define RNN_SMEM_BYTES  (RNN_SMEM_FLOATS * 4)

__global__ __launch_bounds__(256, 1)
void rnn_recurrence(const int*   __restrict__ tokens,
                    const float* __restrict__ Wh) {
    extern __shared__ float sm[];
    float* Wsm  = sm;                          // D * WSM_STR
    float* hbuf = sm + D * WSM_STR;            // 2 * D (double buffer)
    int*   toks = (int*)(sm + D * WSM_STR + 2 * D); // T + 1 (padded)

    const int b = blockIdx.x;
    const int d = threadIdx.x;

    // tokens row -> smem
    const int* trow = tokens + b * T;
    for (int i = d; i < T; i += 256) toks[i] = trow[i];
    if (d == 0) toks[T] = trow[T - 1];

    // SMEM half of Wh (cols 160..255)
    for (int idx = d; idx < D * WSM_K; idx += 256) {
        int r = idx / WSM_K;
        int c = idx - r * WSM_K;
        Wsm[r * WSM_STR + c] = Wh[(r << 8) + WREG_K + c];
    }

    // Register half of Wh (cols 0..159) for output dim d
    float4 wreg[WREG_K / 4];
    const float4* wg = (const float4*)(Wh + (d << 8));
#pragma unroll
    for (int q = 0; q < WREG_K / 4; q++) wreg[q] = wg[q];

    hbuf[d] = 0.0f;
    hbuf[D + d] = 0.0f;
    __syncthreads();

    // software pipeline: current-step table values in regs
    int   tok0 = toks[0];
    float wx = g_EWx[(tok0 << 8) + d];
    float g  = g_EG [(tok0 << 8) + d];

    float* outp = g_out + ((size_t)b * T) * D + d;
    const float* wsrow = Wsm + d * WSM_STR;

    int cur = 0;
    for (int t = 0; t < T; t++) {
        // prefetch next step's table rows (latency hidden under FMAs)
        int   tokn = toks[t + 1];
        float wxn = g_EWx[(tokn << 8) + d];
        float gn  = g_EG [(tokn << 8) + d];

        const float* hb = hbuf + (cur << 8);
        float a0 = wx, a1 = 0.f, a2 = 0.f, a3 = 0.f;
#pragma unroll
        for (int q = 0; q < WREG_K / 4; q++) {
            float4 h4 = *(const float4*)(hb + (q << 2));
            float4 w4 = wreg[q];
            a0 += w4.x * h4.x;
            a1 += w4.y * h4.y;
            a2 += w4.z * h4.z;
            a3 += w4.w * h4.w;
        }
#pragma unroll
        for (int q = 0; q < WSM_K / 4; q++) {
            float4 h4 = *(const float4*)(hb + WREG_K + (q << 2));
            float4 w4 = *(const float4*)(wsrow + (q << 2));
            a0 += w4.x * h4.x;
            a1 += w4.y * h4.y;
            a2 += w4.z * h4.z;
            a3 += w4.w * h4.w;
        }
        float hn = tanhf((a0 + a1) + (a2 + a3));
        outp[(size_t)t * D] = hn * g;

        cur ^= 1;
        hbuf[(cur << 8) + d] = hn;
        __syncthreads();

        wx = wxn;
        g  = gn;
    }
}

// ---------------------------------------------------------------------------
// Kernel 3: logits = out @ E^T.  C[m][v] = sum_k out[m][k] * E[v][k]
// Classic 128x128x8 SGEMM, 256 threads, 8x8 per-thread tile.
// ---------------------------------------------------------------------------
__global__ __launch_bounds__(256)
void logits_gemm(const float* __restrict__ E, float* __restrict__ C) {
    __shared__ float As[8][128];
    __shared__ float Bs[8][128];

    const float* A = g_out;
    const int m0 = blockIdx.x << 7;
    const int v0 = blockIdx.y << 7;
    const int tid = threadIdx.x;

    const int lr = tid >> 1;          // load row 0..127
    const int lc = (tid & 1) << 2;    // load col 0 or 4
    const int tm = (tid >> 4) << 3;   // thread tile row base
    const int tv = (tid & 15) << 3;   // thread tile col base

    float acc[8][8];
#pragma unroll
    for (int i = 0; i < 8; i++)
#pragma unroll
        for (int j = 0; j < 8; j++) acc[i][j] = 0.f;

    const float* Ag = A + (size_t)(m0 + lr) * D + lc;
    const float* Bg = E + (v0 + lr) * D + lc;

    for (int k0 = 0; k0 < D; k0 += 8) {
        float4 a4 = *(const float4*)(Ag + k0);
        float4 b4 = *(const float4*)(Bg + k0);
        As[lc + 0][lr] = a4.x; As[lc + 1][lr] = a4.y;
        As[lc + 2][lr] = a4.z; As[lc + 3][lr] = a4.w;
        Bs[lc + 0][lr] = b4.x; Bs[lc + 1][lr] = b4.y;
        Bs[lc + 2][lr] = b4.z; Bs[lc + 3][lr] = b4.w;
        __syncthreads();
#pragma unroll
        for (int kk = 0; kk < 8; kk++) {
            float ar[8], br[8];
#pragma unroll
            for (int i = 0; i < 8; i++) ar[i] = As[kk][tm + i];
#pragma unroll
            for (int j = 0; j < 8; j++) br[j] = Bs[kk][tv + j];
#pragma unroll
            for (int i = 0; i < 8; i++)
#pragma unroll
                for (int j = 0; j < 8; j++) acc[i][j] += ar[i] * br[j];
        }
        __syncthreads();
    }

#pragma unroll
    for (int i = 0; i < 8; i++) {
        float* Cp = C + (size_t)(m0 + tm + i) * V + v0 + tv;
        *(float4*)(Cp)     = make_float4(acc[i][0], acc[i][1], acc[i][2], acc[i][3]);
        *(float4*)(Cp + 4) = make_float4(acc[i][4], acc[i][5], acc[i][6], acc[i][7]);
    }
}

// ---------------------------------------------------------------------------
extern "C" void kernel_launch(void* const* d_in, const int* in_sizes, int n_in,
                              void* d_out, int out_size) {
    const int*   tokens = (const int*)  d_in[0];
    const float* E      = (const float*)d_in[1];
    const float* Wx     = (const float*)d_in[2];
    const float* Wh     = (const float*)d_in[3];
    const float* Wz     = (const float*)d_in[4];
    float* logits = (float*)d_out;

    precompute_tables<<<V, 256>>>(E, Wx, Wz);

    cudaFuncSetAttribute(rnn_recurrence,
                         cudaFuncAttributeMaxDynamicSharedMemorySize,
                         RNN_SMEM_BYTES);
    rnn_recurrence<<<B, 256, RNN_SMEM_BYTES>>>(tokens, Wh);

    dim3 ggrid((B * T) / 128, V / 128);
    logits_gemm<<<ggrid, 256>>>(E, logits);
}